// round 15
// baseline (speedup 1.0000x reference)
#include <cuda_runtime.h>
#include <cuda_fp16.h>
#include <math.h>
#include <stdint.h>

#define BT     4096      // B*T
#define DMODEL 1024
#define QKVN   3072
#define HEADS  16
#define DHEAD  64
#define TSEQ   2048
#define NBATCH 2
#define NKT    (TSEQ / 64)   // 32 kv tiles
#define QSCALE 0.18033688011112042f   // 0.125 * log2(e), folded into Q

// Scratch (allocation-free rule: __device__ globals)
__device__ __half g_qkvh [(size_t)BT * QKVN];      // fp16 qkv (Q pre-scaled)
__device__ __half g_attnh[(size_t)BT * DMODEL];    // fp16 attention out
__device__ __half g_xh   [(size_t)BT * DMODEL];    // fp16 x
__device__ __half g_wqh  [(size_t)QKVN * DMODEL];  // fp16 w_qkv
__device__ __half g_wph  [(size_t)DMODEL * DMODEL];// fp16 w_proj

__device__ __forceinline__ uint32_t smem_u32(const void* p) {
    uint32_t a;
    asm("{ .reg .u64 t; cvta.to.shared.u64 t, %1; cvt.u32.u64 %0, t; }"
        : "=r"(a) : "l"(p));
    return a;
}

// fast exp2 via MUFU.EX2 (what __expf lowers to, sans the pre-multiply)
__device__ __forceinline__ float ex2(float x) {
    float r;
    asm("ex2.approx.f32 %0, %1;" : "=f"(r) : "f"(x));
    return r;
}

// mma.sync m16n8k16 fp16 with fp32 accumulate
__device__ __forceinline__ void mma_f16(float* d, const uint32_t* a, const uint32_t* b) {
    asm volatile(
        "mma.sync.aligned.m16n8k16.row.col.f32.f16.f16.f32 "
        "{%0,%1,%2,%3}, {%4,%5,%6,%7}, {%8,%9}, {%0,%1,%2,%3};"
        : "+f"(d[0]), "+f"(d[1]), "+f"(d[2]), "+f"(d[3])
        : "r"(a[0]), "r"(a[1]), "r"(a[2]), "r"(a[3]), "r"(b[0]), "r"(b[1]));
}

__device__ __forceinline__ void ldsm_x4(uint32_t* r, uint32_t addr) {
    asm volatile("ldmatrix.sync.aligned.m8n8.x4.shared.b16 {%0,%1,%2,%3}, [%4];"
        : "=r"(r[0]), "=r"(r[1]), "=r"(r[2]), "=r"(r[3]) : "r"(addr));
}
__device__ __forceinline__ void ldsm_x4_t(uint32_t* r, uint32_t addr) {
    asm volatile("ldmatrix.sync.aligned.m8n8.x4.trans.shared.b16 {%0,%1,%2,%3}, [%4];"
        : "=r"(r[0]), "=r"(r[1]), "=r"(r[2]), "=r"(r[3]) : "r"(addr));
}

// ---------------------------------------------------------------------------
// C[M,N] = A[M,K] * B[N,K]^T, fp16 operands, fp32 accum.
// 512 threads, CTA tile 128x256, BK=64 halves (4 k16 steps), 3-stage cp.async
// (2-deep prefetch), one __syncthreads per chunk -> 64 mma between barriers.
// 16 warps 2(m)x8(n), warp tile 64x32. B-frags via ldmatrix.x4 pairs.
// Dyn smem: 3 stages * (128+256) rows * 72 halves * 2B = 165888 B.
// qscale: multiply output cols [0, DMODEL) by QSCALE (folds softmax scale
// into Q at the QKV projection).
// ---------------------------------------------------------------------------
#define GS   72
#define GSTG ((128 + 256) * GS)      // halves per stage (A then B)
#define GEMM_SMEM (3 * GSTG * 2)     // 165888 bytes

__global__ __launch_bounds__(512, 1) void gemm_f16(
    const __half* __restrict__ A, const __half* __restrict__ B,
    float* __restrict__ Cf, __half* __restrict__ Ch, int M, int N, int K,
    int qscale)
{
    extern __shared__ __half gsm[];

    const int tid  = threadIdx.x;
    const int lane = tid & 31;
    const int wid  = tid >> 5;
    const int wm   = wid >> 3;          // 0..1
    const int wn   = wid & 7;           // 0..7
    const int bn   = blockIdx.x;
    const int bm   = blockIdx.y;
    const int KT   = K >> 6;            // BK = 64 halves

    const __half* Ag = A + (size_t)bm * 128 * K;
    const __half* Bg = B + (size_t)bn * 256 * K;

    float acc[4][4][4];
#pragma unroll
    for (int mi = 0; mi < 4; ++mi)
#pragma unroll
        for (int ni = 0; ni < 4; ++ni)
#pragma unroll
            for (int r = 0; r < 4; ++r) acc[mi][ni][r] = 0.f;

    auto fill = [&](int kt) {
        const int st = kt % 3;
        __half* sA = gsm + st * GSTG;
        __half* sB = sA + 128 * GS;
        const int k0 = kt << 6;
        // A: 128 rows x 64 halves = 1024 chunks of 16B, two per thread
#pragma unroll
        for (int u = 0; u < 2; ++u) {
            int f   = u * 512 + tid;
            int row = f >> 3;
            int col = (f & 7) << 3;
            uint32_t da = smem_u32(sA + row * GS + col);
            const __half* sa = Ag + (size_t)row * K + k0 + col;
            asm volatile("cp.async.cg.shared.global [%0], [%1], 16;" :: "r"(da), "l"(sa));
        }
        // B: 256 rows x 64 halves = 2048 chunks, four per thread
#pragma unroll
        for (int u = 0; u < 4; ++u) {
            int f   = u * 512 + tid;
            int row = f >> 3;
            int col = (f & 7) << 3;
            uint32_t db = smem_u32(sB + row * GS + col);
            const __half* sb = Bg + (size_t)row * K + k0 + col;
            asm volatile("cp.async.cg.shared.global [%0], [%1], 16;" :: "r"(db), "l"(sb));
        }
        asm volatile("cp.async.commit_group;" ::: "memory");
    };

    fill(0); fill(1);

    const int lane15 = lane & 15;
    const int hi8    = (lane >> 4) << 3;   // 0 / 8
    const int lr = lane >> 2;
    const int lc = lane & 3;

    for (int kt = 0; kt < KT; ++kt) {
        if (kt + 1 < KT) asm volatile("cp.async.wait_group 1;" ::: "memory");
        else             asm volatile("cp.async.wait_group 0;" ::: "memory");
        __syncthreads();  // chunk kt visible; all warps done reading stage (kt-1)%3

        if (kt + 2 < KT) fill(kt + 2);

        const int st = kt % 3;
        const __half* sA = gsm + st * GSTG;
        const __half* sB = sA + 128 * GS;
#pragma unroll
        for (int ks = 0; ks < 4; ++ks) {
            const int k0 = ks << 4;
            uint32_t af[4][4], bf[4][2];
#pragma unroll
            for (int mi = 0; mi < 4; ++mi)
                ldsm_x4(af[mi], smem_u32(sA + (wm * 64 + mi * 16 + lane15) * GS
                                            + k0 + hi8));
#pragma unroll
            for (int p = 0; p < 2; ++p) {
                uint32_t t[4];
                ldsm_x4(t, smem_u32(sB + (wn * 32 + p * 16 + lane15) * GS
                                       + k0 + hi8));
                bf[2 * p][0]     = t[0]; bf[2 * p][1]     = t[2];
                bf[2 * p + 1][0] = t[1]; bf[2 * p + 1][1] = t[3];
            }
#pragma unroll
            for (int mi = 0; mi < 4; ++mi)
#pragma unroll
                for (int ni = 0; ni < 4; ++ni)
                    mma_f16(acc[mi][ni], af[mi], bf[ni]);
        }
    }

#pragma unroll
    for (int mi = 0; mi < 4; ++mi) {
#pragma unroll
        for (int ni = 0; ni < 4; ++ni) {
            const int r0 = bm * 128 + wm * 64 + mi * 16 + lr;
            const int c0 = bn * 256 + wn * 32 + ni * 8 + lc * 2;
            float sc = (qscale && c0 < DMODEL) ? QSCALE : 1.f;
            float v0 = acc[mi][ni][0] * sc, v1 = acc[mi][ni][1] * sc;
            float v2 = acc[mi][ni][2] * sc, v3 = acc[mi][ni][3] * sc;
            if (Ch) {
                *(__half2*)(Ch + (size_t)r0 * N + c0) = __floats2half2_rn(v0, v1);
                *(__half2*)(Ch + (size_t)(r0 + 8) * N + c0) = __floats2half2_rn(v2, v3);
            } else {
                *(float2*)(Cf + (size_t)r0 * N + c0)       = make_float2(v0, v1);
                *(float2*)(Cf + (size_t)(r0 + 8) * N + c0) = make_float2(v2, v3);
            }
        }
    }
}

// ---------------------------------------------------------------------------
// Merged f32 -> fp16 conversion of all three operand tensors.
// ---------------------------------------------------------------------------
#define X4  ((BT * DMODEL) / 4)
#define WQ4 ((QKVN * DMODEL) / 4)
#define WP4 ((DMODEL * DMODEL) / 4)

__global__ __launch_bounds__(256) void cvt_all_kernel(
    const float* __restrict__ x, const float* __restrict__ wq,
    const float* __restrict__ wp)
{
    int i = blockIdx.x * blockDim.x + threadIdx.x;
    const float4* src;
    __half2* dst;
    int j;
    if (i < X4)                  { src = (const float4*)x;  dst = (__half2*)g_xh;  j = i; }
    else if (i < X4 + WQ4)       { src = (const float4*)wq; dst = (__half2*)g_wqh; j = i - X4; }
    else if (i < X4 + WQ4 + WP4) { src = (const float4*)wp; dst = (__half2*)g_wph; j = i - X4 - WQ4; }
    else return;
    float4 v = src[j];
    dst[2 * j]     = __floats2half2_rn(v.x, v.y);
    dst[2 * j + 1] = __floats2half2_rn(v.z, v.w);
}

// ---------------------------------------------------------------------------
// FA2-style fp16 flash attention, softmax in registers.
// Q pre-scaled by 0.125*log2(e) -> softmax is pure ex2.approx.
// K-frags via ldmatrix.x4 pairs; V-frags via ldmatrix.x4.trans pairs.
// ---------------------------------------------------------------------------
#define AQS 72
#define ATTN_SMEM ((128 * AQS + 4 * 64 * AQS) * 2)

__global__ __launch_bounds__(256, 2) void attn_f16(__half* __restrict__ out)
{
    extern __shared__ __align__(16) __half ash[];
    __half* Qs = ash;                    // [128][72]
    __half* Kb = Qs + 128 * AQS;         // [2][64][72]
    __half* Vb = Kb + 2 * 64 * AQS;      // [2][64][72]

    const int qt   = blockIdx.x;
    const int h    = blockIdx.y;
    const int b    = blockIdx.z;
    const int tid  = threadIdx.x;
    const int lane = tid & 31;
    const int wid  = tid >> 5;          // warp owns q-rows [wid*16, wid*16+16)
    const int lr   = lane >> 2;
    const int lc   = lane & 3;
    const int lane15 = lane & 15;
    const int hi8    = (lane >> 4) << 3;

    const size_t base = (size_t)b * TSEQ * QKVN;

    auto load_kv = [&](int kt) {
        __half* kd = Kb + (kt & 1) * 64 * AQS;
        __half* vd = Vb + (kt & 1) * 64 * AQS;
        const size_t krow = base + (size_t)(kt * 64) * QKVN + DMODEL + h * DHEAD;
        const size_t vrow = base + (size_t)(kt * 64) * QKVN + 2 * DMODEL + h * DHEAD;
#pragma unroll
        for (int u = 0; u < 2; ++u) {
            int c   = u * 256 + tid;
            int row = c >> 3;
            int col = (c & 7) << 3;
            uint32_t dk = smem_u32(kd + row * AQS + col);
            uint32_t dv = smem_u32(vd + row * AQS + col);
            const __half* sk = g_qkvh + krow + (size_t)row * QKVN + col;
            const __half* sv = g_qkvh + vrow + (size_t)row * QKVN + col;
            asm volatile("cp.async.cg.shared.global [%0], [%1], 16;" :: "r"(dk), "l"(sk));
            asm volatile("cp.async.cg.shared.global [%0], [%1], 16;" :: "r"(dv), "l"(sv));
        }
        asm volatile("cp.async.commit_group;" ::: "memory");
    };

    // prologue: Q tile (128x64) + K0/V0
#pragma unroll
    for (int u = 0; u < 4; ++u) {
        int c   = u * 256 + tid;
        int row = c >> 3;
        int col = (c & 7) << 3;
        uint32_t d = smem_u32(Qs + row * AQS + col);
        const __half* s = g_qkvh + base + (size_t)(qt * 128 + row) * QKVN + h * DHEAD + col;
        asm volatile("cp.async.cg.shared.global [%0], [%1], 16;" :: "r"(d), "l"(s));
    }
    asm volatile("cp.async.commit_group;" ::: "memory");
    load_kv(0);
    asm volatile("cp.async.wait_group 0;" ::: "memory");
    __syncthreads();

    uint32_t qf[4][4];
#pragma unroll
    for (int kc = 0; kc < 4; ++kc)
        ldsm_x4(qf[kc], smem_u32(Qs + (wid * 16 + lane15) * AQS + kc * 16 + hi8));

    float m0 = -INFINITY, m1 = -INFINITY, l0 = 0.f, l1 = 0.f;
    float o[8][4];
#pragma unroll
    for (int nb = 0; nb < 8; ++nb)
#pragma unroll
        for (int r = 0; r < 4; ++r) o[nb][r] = 0.f;

    for (int kt = 0; kt < NKT; ++kt) {
        if (kt + 1 < NKT) load_kv(kt + 1);

        const __half* Ks = Kb + (kt & 1) * 64 * AQS;
        const __half* Vs = Vb + (kt & 1) * 64 * AQS;

        // ---- S = Q * K^T ----
        float s[8][4];
#pragma unroll
        for (int nb = 0; nb < 8; ++nb)
#pragma unroll
            for (int r = 0; r < 4; ++r) s[nb][r] = 0.f;

#pragma unroll
        for (int kc = 0; kc < 4; ++kc) {
            uint32_t bf[8][2];
#pragma unroll
            for (int p = 0; p < 4; ++p) {
                uint32_t t[4];
                ldsm_x4(t, smem_u32(Ks + (p * 16 + lane15) * AQS + kc * 16 + hi8));
                bf[2 * p][0]     = t[0]; bf[2 * p][1]     = t[2];
                bf[2 * p + 1][0] = t[1]; bf[2 * p + 1][1] = t[3];
            }
#pragma unroll
            for (int nb = 0; nb < 8; ++nb)
                mma_f16(s[nb], qf[kc], bf[nb]);
        }

        // ---- online softmax (ex2; scale pre-folded into Q) ----
        float mx0 = s[0][0], mx1 = s[0][2];
#pragma unroll
        for (int nb = 0; nb < 8; ++nb) {
            mx0 = fmaxf(mx0, fmaxf(s[nb][0], s[nb][1]));
            mx1 = fmaxf(mx1, fmaxf(s[nb][2], s[nb][3]));
        }
        mx0 = fmaxf(mx0, __shfl_xor_sync(0xffffffffu, mx0, 1));
        mx0 = fmaxf(mx0, __shfl_xor_sync(0xffffffffu, mx0, 2));
        mx1 = fmaxf(mx1, __shfl_xor_sync(0xffffffffu, mx1, 1));
        mx1 = fmaxf(mx1, __shfl_xor_sync(0xffffffffu, mx1, 2));

        const float mn0 = fmaxf(m0, mx0);
        const float mn1 = fmaxf(m1, mx1);
        const float e0 = ex2(m0 - mn0);
        const float e1 = ex2(m1 - mn1);
        m0 = mn0; m1 = mn1;

        uint32_t pf[4][4];
        float ls0 = 0.f, ls1 = 0.f;
#pragma unroll
        for (int kc = 0; kc < 4; ++kc) {
#pragma unroll
            for (int half_id = 0; half_id < 2; ++half_id) {
                const int nb = 2 * kc + half_id;
                float p00 = ex2(s[nb][0] - mn0);
                float p01 = ex2(s[nb][1] - mn0);
                float p10 = ex2(s[nb][2] - mn1);
                float p11 = ex2(s[nb][3] - mn1);
                __half2 h0 = __floats2half2_rn(p00, p01);
                __half2 h1 = __floats2half2_rn(p10, p11);
                ls0 += __low2float(h0) + __high2float(h0);
                ls1 += __low2float(h1) + __high2float(h1);
                pf[kc][half_id * 2]     = *(uint32_t*)&h0;
                pf[kc][half_id * 2 + 1] = *(uint32_t*)&h1;
            }
        }
        ls0 += __shfl_xor_sync(0xffffffffu, ls0, 1);
        ls0 += __shfl_xor_sync(0xffffffffu, ls0, 2);
        ls1 += __shfl_xor_sync(0xffffffffu, ls1, 1);
        ls1 += __shfl_xor_sync(0xffffffffu, ls1, 2);
        l0 = l0 * e0 + ls0;
        l1 = l1 * e1 + ls1;

#pragma unroll
        for (int nb = 0; nb < 8; ++nb) {
            o[nb][0] *= e0; o[nb][1] *= e0;
            o[nb][2] *= e1; o[nb][3] *= e1;
        }

        // ---- O += P * V (x4.trans pairs) ----
#pragma unroll
        for (int kc = 0; kc < 4; ++kc) {
            uint32_t bv[8][2];
#pragma unroll
            for (int p = 0; p < 4; ++p) {
                uint32_t t[4];
                ldsm_x4_t(t, smem_u32(Vs + (kc * 16 + lane15) * AQS + p * 16 + hi8));
                bv[2 * p][0]     = t[0]; bv[2 * p][1]     = t[1];
                bv[2 * p + 1][0] = t[2]; bv[2 * p + 1][1] = t[3];
            }
#pragma unroll
            for (int nb = 0; nb < 8; ++nb)
                mma_f16(o[nb], pf[kc], bv[nb]);
        }

        if (kt + 1 < NKT) {
            asm volatile("cp.async.wait_group 0;" ::: "memory");
            __syncthreads();
        }
    }

    const float inv0 = 1.f / l0;
    const float inv1 = 1.f / l1;
    const size_t r0 = (size_t)b * TSEQ + qt * 128 + wid * 16 + lr;
#pragma unroll
    for (int nb = 0; nb < 8; ++nb) {
        const int c0 = h * DHEAD + nb * 8 + lc * 2;
        *(__half2*)(out + r0 * DMODEL + c0) =
            __floats2half2_rn(o[nb][0] * inv0, o[nb][1] * inv0);
        *(__half2*)(out + (r0 + 8) * DMODEL + c0) =
            __floats2half2_rn(o[nb][2] * inv1, o[nb][3] * inv1);
    }
}

// ---------------------------------------------------------------------------
extern "C" void kernel_launch(void* const* d_in, const int* in_sizes, int n_in,
                              void* d_out, int out_size)
{
    const float* x      = (const float*)d_in[0];   // [2,2048,1024]
    const float* w_qkv  = (const float*)d_in[1];   // [3072,1024]
    const float* w_proj = (const float*)d_in[2];   // [1024,1024]
    float* out = (float*)d_out;                    // [2,2048,1024]

    __half *qkvh, *attnh, *xh, *wqh, *wph;
    cudaGetSymbolAddress((void**)&qkvh,  g_qkvh);
    cudaGetSymbolAddress((void**)&attnh, g_attnh);
    cudaGetSymbolAddress((void**)&xh,    g_xh);
    cudaGetSymbolAddress((void**)&wqh,   g_wqh);
    cudaGetSymbolAddress((void**)&wph,   g_wph);

    cudaFuncSetAttribute(gemm_f16,
                         cudaFuncAttributeMaxDynamicSharedMemorySize, GEMM_SMEM);
    cudaFuncSetAttribute(attn_f16,
                         cudaFuncAttributeMaxDynamicSharedMemorySize, ATTN_SMEM);

    // 0) f32 -> fp16 conversion of all operands (one launch)
    {
        int total = X4 + WQ4 + WP4;
        cvt_all_kernel<<<(total + 255) / 256, 256>>>(x, w_qkv, w_proj);
    }

    // 1) QKV projection -> fp16 qkv (Q columns pre-scaled by QSCALE)
    {
        dim3 g(QKVN / 256, BT / 128);
        gemm_f16<<<g, 512, GEMM_SMEM>>>(xh, wqh, nullptr, qkvh, BT, QKVN, DMODEL, 1);
    }

    // 2) FA2-style fp16 flash attention -> fp16 attn
    {
        dim3 ga(TSEQ / 128, HEADS, NBATCH);
        attn_f16<<<ga, 256, ATTN_SMEM>>>(attnh);
    }

    // 3) Output projection -> fp32 out
    {
        dim3 g(DMODEL / 256, BT / 128);
        gemm_f16<<<g, 512, GEMM_SMEM>>>(attnh, wph, out, nullptr, BT, DMODEL, DMODEL, 0);
    }
}

// round 16
// speedup vs baseline: 1.4841x; 1.4841x over previous
#include <cuda_runtime.h>
#include <cuda_fp16.h>
#include <math.h>
#include <stdint.h>

#define BT     4096      // B*T
#define DMODEL 1024
#define QKVN   3072
#define HEADS  16
#define DHEAD  64
#define TSEQ   2048
#define NBATCH 2
#define NKT    (TSEQ / 64)   // 32 kv tiles
#define QSCALE 0.18033688011112042f   // 0.125 * log2(e), folded into Q

// Scratch (allocation-free rule: __device__ globals)
__device__ __half g_qkvh [(size_t)BT * QKVN];      // fp16 qkv (Q pre-scaled)
__device__ __half g_attnh[(size_t)BT * DMODEL];    // fp16 attention out
__device__ __half g_xh   [(size_t)BT * DMODEL];    // fp16 x
__device__ __half g_wqh  [(size_t)QKVN * DMODEL];  // fp16 w_qkv
__device__ __half g_wph  [(size_t)DMODEL * DMODEL];// fp16 w_proj

__device__ __forceinline__ uint32_t smem_u32(const void* p) {
    uint32_t a;
    asm("{ .reg .u64 t; cvta.to.shared.u64 t, %1; cvt.u32.u64 %0, t; }"
        : "=r"(a) : "l"(p));
    return a;
}

// fast exp2 via MUFU.EX2
__device__ __forceinline__ float ex2(float x) {
    float r;
    asm("ex2.approx.f32 %0, %1;" : "=f"(r) : "f"(x));
    return r;
}

// mma.sync m16n8k16 fp16 with fp32 accumulate
__device__ __forceinline__ void mma_f16(float* d, const uint32_t* a, const uint32_t* b) {
    asm volatile(
        "mma.sync.aligned.m16n8k16.row.col.f32.f16.f16.f32 "
        "{%0,%1,%2,%3}, {%4,%5,%6,%7}, {%8,%9}, {%0,%1,%2,%3};"
        : "+f"(d[0]), "+f"(d[1]), "+f"(d[2]), "+f"(d[3])
        : "r"(a[0]), "r"(a[1]), "r"(a[2]), "r"(a[3]), "r"(b[0]), "r"(b[1]));
}

__device__ __forceinline__ void ldsm_x4(uint32_t* r, uint32_t addr) {
    asm volatile("ldmatrix.sync.aligned.m8n8.x4.shared.b16 {%0,%1,%2,%3}, [%4];"
        : "=r"(r[0]), "=r"(r[1]), "=r"(r[2]), "=r"(r[3]) : "r"(addr));
}
__device__ __forceinline__ void ldsm_x2(uint32_t* r, uint32_t addr) {
    asm volatile("ldmatrix.sync.aligned.m8n8.x2.shared.b16 {%0,%1}, [%2];"
        : "=r"(r[0]), "=r"(r[1]) : "r"(addr));
}
__device__ __forceinline__ void ldsm_x2_t(uint32_t* r, uint32_t addr) {
    asm volatile("ldmatrix.sync.aligned.m8n8.x2.trans.shared.b16 {%0,%1}, [%2];"
        : "=r"(r[0]), "=r"(r[1]) : "r"(addr));
}

// ---------------------------------------------------------------------------
// C[M,N] = A[M,K] * B[N,K]^T, fp16 operands, fp32 accum. (exact R11 kernel,
// + qscale epilogue: multiply output cols [0, DMODEL) by QSCALE)
// 128x128 CTA tile, BK=32 halves, 4-stage cp.async, one sync per chunk.
// 8 warps 2(m)x4(n), warp tile 64x32. smem row stride 40 halves.
// ---------------------------------------------------------------------------
#define GS   40
#define GSTG (2 * 128 * GS)          // halves per stage (A+B)
#define GEMM_SMEM (4 * GSTG * 2)     // 81920 bytes

__global__ __launch_bounds__(256, 2) void gemm_f16(
    const __half* __restrict__ A, const __half* __restrict__ B,
    float* __restrict__ Cf, __half* __restrict__ Ch, int M, int N, int K,
    int qscale)
{
    extern __shared__ __half gsm[];

    const int tid  = threadIdx.x;
    const int lane = tid & 31;
    const int wid  = tid >> 5;
    const int wm   = wid >> 2;
    const int wn   = wid & 3;
    const int bn   = blockIdx.x;
    const int bm   = blockIdx.y;
    const int KT   = K >> 5;

    const __half* Ag = A + (size_t)bm * 128 * K;
    const __half* Bg = B + (size_t)bn * 128 * K;

    float acc[4][4][4];
#pragma unroll
    for (int mi = 0; mi < 4; ++mi)
#pragma unroll
        for (int ni = 0; ni < 4; ++ni)
#pragma unroll
            for (int r = 0; r < 4; ++r) acc[mi][ni][r] = 0.f;

    auto fill = [&](int kt) {
        const int st = kt & 3;
        __half* sA = gsm + st * GSTG;
        __half* sB = sA + 128 * GS;
        const int k0 = kt << 5;
#pragma unroll
        for (int u = 0; u < 2; ++u) {
            int f   = u * 256 + tid;
            int row = f >> 2;
            int col = (f & 3) << 3;
            uint32_t da = smem_u32(sA + row * GS + col);
            uint32_t db = smem_u32(sB + row * GS + col);
            const __half* sa = Ag + (size_t)row * K + k0 + col;
            const __half* sb = Bg + (size_t)row * K + k0 + col;
            asm volatile("cp.async.cg.shared.global [%0], [%1], 16;" :: "r"(da), "l"(sa));
            asm volatile("cp.async.cg.shared.global [%0], [%1], 16;" :: "r"(db), "l"(sb));
        }
        asm volatile("cp.async.commit_group;" ::: "memory");
    };

    fill(0); fill(1); fill(2);

    const int lane15 = lane & 15;
    const int a_col  = (lane >> 4) << 3;
    const int b_row  = lane & 7;
    const int b_col  = ((lane >> 3) & 1) << 3;
    const int lr = lane >> 2;
    const int lc = lane & 3;

    for (int kt = 0; kt < KT; ++kt) {
        const int rem = KT - 1 - kt;
        if (rem >= 2)      asm volatile("cp.async.wait_group 2;" ::: "memory");
        else if (rem == 1) asm volatile("cp.async.wait_group 1;" ::: "memory");
        else               asm volatile("cp.async.wait_group 0;" ::: "memory");
        __syncthreads();

        if (kt + 3 < KT) fill(kt + 3);

        const int st = kt & 3;
        const __half* sA = gsm + st * GSTG;
        const __half* sB = sA + 128 * GS;
#pragma unroll
        for (int ks = 0; ks < 2; ++ks) {
            const int k0 = ks << 4;
            uint32_t af[4][4], bf[4][2];
#pragma unroll
            for (int mi = 0; mi < 4; ++mi)
                ldsm_x4(af[mi], smem_u32(sA + (wm * 64 + mi * 16 + lane15) * GS
                                            + k0 + a_col));
#pragma unroll
            for (int ni = 0; ni < 4; ++ni)
                ldsm_x2(bf[ni], smem_u32(sB + (wn * 32 + ni * 8 + b_row) * GS
                                            + k0 + b_col));
#pragma unroll
            for (int mi = 0; mi < 4; ++mi)
#pragma unroll
                for (int ni = 0; ni < 4; ++ni)
                    mma_f16(acc[mi][ni], af[mi], bf[ni]);
        }
    }

#pragma unroll
    for (int mi = 0; mi < 4; ++mi) {
#pragma unroll
        for (int ni = 0; ni < 4; ++ni) {
            const int r0 = bm * 128 + wm * 64 + mi * 16 + lr;
            const int c0 = bn * 128 + wn * 32 + ni * 8 + lc * 2;
            const float sc = (qscale && c0 < DMODEL) ? QSCALE : 1.f;
            const float v0 = acc[mi][ni][0] * sc, v1 = acc[mi][ni][1] * sc;
            const float v2 = acc[mi][ni][2] * sc, v3 = acc[mi][ni][3] * sc;
            if (Ch) {
                *(__half2*)(Ch + (size_t)r0 * N + c0) = __floats2half2_rn(v0, v1);
                *(__half2*)(Ch + (size_t)(r0 + 8) * N + c0) = __floats2half2_rn(v2, v3);
            } else {
                *(float2*)(Cf + (size_t)r0 * N + c0)       = make_float2(v0, v1);
                *(float2*)(Cf + (size_t)(r0 + 8) * N + c0) = make_float2(v2, v3);
            }
        }
    }
}

// ---------------------------------------------------------------------------
// Merged f32 -> fp16 conversion of all three operand tensors.
// ---------------------------------------------------------------------------
#define X4  ((BT * DMODEL) / 4)
#define WQ4 ((QKVN * DMODEL) / 4)
#define WP4 ((DMODEL * DMODEL) / 4)

__global__ __launch_bounds__(256) void cvt_all_kernel(
    const float* __restrict__ x, const float* __restrict__ wq,
    const float* __restrict__ wp)
{
    int i = blockIdx.x * blockDim.x + threadIdx.x;
    const float4* src;
    __half2* dst;
    int j;
    if (i < X4)                  { src = (const float4*)x;  dst = (__half2*)g_xh;  j = i; }
    else if (i < X4 + WQ4)       { src = (const float4*)wq; dst = (__half2*)g_wqh; j = i - X4; }
    else if (i < X4 + WQ4 + WP4) { src = (const float4*)wp; dst = (__half2*)g_wph; j = i - X4 - WQ4; }
    else return;
    float4 v = src[j];
    dst[2 * j]     = __floats2half2_rn(v.x, v.y);
    dst[2 * j + 1] = __floats2half2_rn(v.z, v.w);
}

// ---------------------------------------------------------------------------
// FA2-style fp16 flash attention (R11 structure; softmax via ex2 with
// Q pre-scaled by 0.125*log2(e) in the QKV GEMM epilogue).
// ---------------------------------------------------------------------------
#define AQS 72
#define ATTN_SMEM ((128 * AQS + 4 * 64 * AQS) * 2)

__global__ __launch_bounds__(256, 2) void attn_f16(__half* __restrict__ out)
{
    extern __shared__ __align__(16) __half ash[];
    __half* Qs = ash;                    // [128][72]
    __half* Kb = Qs + 128 * AQS;         // [2][64][72]
    __half* Vb = Kb + 2 * 64 * AQS;      // [2][64][72]

    const int qt   = blockIdx.x;
    const int h    = blockIdx.y;
    const int b    = blockIdx.z;
    const int tid  = threadIdx.x;
    const int lane = tid & 31;
    const int wid  = tid >> 5;          // warp owns q-rows [wid*16, wid*16+16)
    const int lr   = lane >> 2;
    const int lc   = lane & 3;
    const int lane15 = lane & 15;
    const int a_col  = (lane >> 4) << 3;
    const int b_row  = lane & 7;
    const int b_col  = ((lane >> 3) & 1) << 3;

    const size_t base = (size_t)b * TSEQ * QKVN;

    auto load_kv = [&](int kt) {
        __half* kd = Kb + (kt & 1) * 64 * AQS;
        __half* vd = Vb + (kt & 1) * 64 * AQS;
        const size_t krow = base + (size_t)(kt * 64) * QKVN + DMODEL + h * DHEAD;
        const size_t vrow = base + (size_t)(kt * 64) * QKVN + 2 * DMODEL + h * DHEAD;
#pragma unroll
        for (int u = 0; u < 2; ++u) {
            int c   = u * 256 + tid;
            int row = c >> 3;
            int col = (c & 7) << 3;
            uint32_t dk = smem_u32(kd + row * AQS + col);
            uint32_t dv = smem_u32(vd + row * AQS + col);
            const __half* sk = g_qkvh + krow + (size_t)row * QKVN + col;
            const __half* sv = g_qkvh + vrow + (size_t)row * QKVN + col;
            asm volatile("cp.async.cg.shared.global [%0], [%1], 16;" :: "r"(dk), "l"(sk));
            asm volatile("cp.async.cg.shared.global [%0], [%1], 16;" :: "r"(dv), "l"(sv));
        }
        asm volatile("cp.async.commit_group;" ::: "memory");
    };

    // prologue: Q tile (128x64) + K0/V0
#pragma unroll
    for (int u = 0; u < 4; ++u) {
        int c   = u * 256 + tid;
        int row = c >> 3;
        int col = (c & 7) << 3;
        uint32_t d = smem_u32(Qs + row * AQS + col);
        const __half* s = g_qkvh + base + (size_t)(qt * 128 + row) * QKVN + h * DHEAD + col;
        asm volatile("cp.async.cg.shared.global [%0], [%1], 16;" :: "r"(d), "l"(s));
    }
    asm volatile("cp.async.commit_group;" ::: "memory");
    load_kv(0);
    asm volatile("cp.async.wait_group 0;" ::: "memory");
    __syncthreads();

    uint32_t qf[4][4];
#pragma unroll
    for (int kc = 0; kc < 4; ++kc)
        ldsm_x4(qf[kc], smem_u32(Qs + (wid * 16 + lane15) * AQS + kc * 16 + a_col));

    float m0 = -INFINITY, m1 = -INFINITY, l0 = 0.f, l1 = 0.f;
    float o[8][4];
#pragma unroll
    for (int nb = 0; nb < 8; ++nb)
#pragma unroll
        for (int r = 0; r < 4; ++r) o[nb][r] = 0.f;

    for (int kt = 0; kt < NKT; ++kt) {
        if (kt + 1 < NKT) load_kv(kt + 1);

        const __half* Ks = Kb + (kt & 1) * 64 * AQS;
        const __half* Vs = Vb + (kt & 1) * 64 * AQS;

        // ---- S = Q * K^T ----
        float s[8][4];
#pragma unroll
        for (int nb = 0; nb < 8; ++nb)
#pragma unroll
            for (int r = 0; r < 4; ++r) s[nb][r] = 0.f;

#pragma unroll
        for (int kc = 0; kc < 4; ++kc) {
            uint32_t bf[8][2];
#pragma unroll
            for (int nb = 0; nb < 8; ++nb)
                ldsm_x2(bf[nb], smem_u32(Ks + (nb * 8 + b_row) * AQS
                                            + kc * 16 + b_col));
#pragma unroll
            for (int nb = 0; nb < 8; ++nb)
                mma_f16(s[nb], qf[kc], bf[nb]);
        }

        // ---- online softmax (ex2; scale pre-folded into Q) ----
        float mx0 = s[0][0], mx1 = s[0][2];
#pragma unroll
        for (int nb = 0; nb < 8; ++nb) {
            mx0 = fmaxf(mx0, fmaxf(s[nb][0], s[nb][1]));
            mx1 = fmaxf(mx1, fmaxf(s[nb][2], s[nb][3]));
        }
        mx0 = fmaxf(mx0, __shfl_xor_sync(0xffffffffu, mx0, 1));
        mx0 = fmaxf(mx0, __shfl_xor_sync(0xffffffffu, mx0, 2));
        mx1 = fmaxf(mx1, __shfl_xor_sync(0xffffffffu, mx1, 1));
        mx1 = fmaxf(mx1, __shfl_xor_sync(0xffffffffu, mx1, 2));

        const float mn0 = fmaxf(m0, mx0);
        const float mn1 = fmaxf(m1, mx1);
        const float e0 = ex2(m0 - mn0);
        const float e1 = ex2(m1 - mn1);
        m0 = mn0; m1 = mn1;

        uint32_t pf[4][4];
        float ls0 = 0.f, ls1 = 0.f;
#pragma unroll
        for (int kc = 0; kc < 4; ++kc) {
#pragma unroll
            for (int half_id = 0; half_id < 2; ++half_id) {
                const int nb = 2 * kc + half_id;
                float p00 = ex2(s[nb][0] - mn0);
                float p01 = ex2(s[nb][1] - mn0);
                float p10 = ex2(s[nb][2] - mn1);
                float p11 = ex2(s[nb][3] - mn1);
                __half2 h0 = __floats2half2_rn(p00, p01);
                __half2 h1 = __floats2half2_rn(p10, p11);
                ls0 += __low2float(h0) + __high2float(h0);
                ls1 += __low2float(h1) + __high2float(h1);
                pf[kc][half_id * 2]     = *(uint32_t*)&h0;
                pf[kc][half_id * 2 + 1] = *(uint32_t*)&h1;
            }
        }
        ls0 += __shfl_xor_sync(0xffffffffu, ls0, 1);
        ls0 += __shfl_xor_sync(0xffffffffu, ls0, 2);
        ls1 += __shfl_xor_sync(0xffffffffu, ls1, 1);
        ls1 += __shfl_xor_sync(0xffffffffu, ls1, 2);
        l0 = l0 * e0 + ls0;
        l1 = l1 * e1 + ls1;

#pragma unroll
        for (int nb = 0; nb < 8; ++nb) {
            o[nb][0] *= e0; o[nb][1] *= e0;
            o[nb][2] *= e1; o[nb][3] *= e1;
        }

        // ---- O += P * V ----
#pragma unroll
        for (int kc = 0; kc < 4; ++kc) {
            uint32_t bv[8][2];
#pragma unroll
            for (int nb = 0; nb < 8; ++nb)
                ldsm_x2_t(bv[nb], smem_u32(Vs + (kc * 16 + lane15) * AQS + nb * 8));
#pragma unroll
            for (int nb = 0; nb < 8; ++nb)
                mma_f16(o[nb], pf[kc], bv[nb]);
        }

        if (kt + 1 < NKT) {
            asm volatile("cp.async.wait_group 0;" ::: "memory");
            __syncthreads();
        }
    }

    const float inv0 = 1.f / l0;
    const float inv1 = 1.f / l1;
    const size_t r0 = (size_t)b * TSEQ + qt * 128 + wid * 16 + lr;
#pragma unroll
    for (int nb = 0; nb < 8; ++nb) {
        const int c0 = h * DHEAD + nb * 8 + lc * 2;
        *(__half2*)(out + r0 * DMODEL + c0) =
            __floats2half2_rn(o[nb][0] * inv0, o[nb][1] * inv0);
        *(__half2*)(out + (r0 + 8) * DMODEL + c0) =
            __floats2half2_rn(o[nb][2] * inv1, o[nb][3] * inv1);
    }
}

// ---------------------------------------------------------------------------
extern "C" void kernel_launch(void* const* d_in, const int* in_sizes, int n_in,
                              void* d_out, int out_size)
{
    const float* x      = (const float*)d_in[0];   // [2,2048,1024]
    const float* w_qkv  = (const float*)d_in[1];   // [3072,1024]
    const float* w_proj = (const float*)d_in[2];   // [1024,1024]
    float* out = (float*)d_out;                    // [2,2048,1024]

    __half *qkvh, *attnh, *xh, *wqh, *wph;
    cudaGetSymbolAddress((void**)&qkvh,  g_qkvh);
    cudaGetSymbolAddress((void**)&attnh, g_attnh);
    cudaGetSymbolAddress((void**)&xh,    g_xh);
    cudaGetSymbolAddress((void**)&wqh,   g_wqh);
    cudaGetSymbolAddress((void**)&wph,   g_wph);

    cudaFuncSetAttribute(gemm_f16,
                         cudaFuncAttributeMaxDynamicSharedMemorySize, GEMM_SMEM);
    cudaFuncSetAttribute(attn_f16,
                         cudaFuncAttributeMaxDynamicSharedMemorySize, ATTN_SMEM);

    // 0) f32 -> fp16 conversion of all operands (one launch)
    {
        int total = X4 + WQ4 + WP4;
        cvt_all_kernel<<<(total + 255) / 256, 256>>>(x, w_qkv, w_proj);
    }

    // 1) QKV projection -> fp16 qkv (Q columns pre-scaled by QSCALE)
    {
        dim3 g(QKVN / 128, BT / 128);
        gemm_f16<<<g, 256, GEMM_SMEM>>>(xh, wqh, nullptr, qkvh, BT, QKVN, DMODEL, 1);
    }

    // 2) FA2-style fp16 flash attention -> fp16 attn
    {
        dim3 ga(TSEQ / 128, HEADS, NBATCH);
        attn_f16<<<ga, 256, ATTN_SMEM>>>(attnh);
    }

    // 3) Output projection -> fp32 out
    {
        dim3 g(DMODEL / 128, BT / 128);
        gemm_f16<<<g, 256, GEMM_SMEM>>>(attnh, wph, out, nullptr, BT, DMODEL, DMODEL, 0);
    }
}

// round 17
// speedup vs baseline: 1.5132x; 1.0196x over previous
#include <cuda_runtime.h>
#include <cuda_fp16.h>
#include <math.h>
#include <stdint.h>

#define BT     4096      // B*T
#define DMODEL 1024
#define QKVN   3072
#define HEADS  16
#define DHEAD  64
#define TSEQ   2048
#define NBATCH 2
#define NKT    (TSEQ / 64)   // 32 kv tiles
#define QSCALE 0.18033688011112042f   // 0.125 * log2(e), folded into Q

// Scratch (allocation-free rule: __device__ globals)
__device__ __half g_qkvh [(size_t)BT * QKVN];      // fp16 qkv (Q pre-scaled)
__device__ __half g_attnh[(size_t)BT * DMODEL];    // fp16 attention out
__device__ __half g_xh   [(size_t)BT * DMODEL];    // fp16 x
__device__ __half g_wqh  [(size_t)QKVN * DMODEL];  // fp16 w_qkv
__device__ __half g_wph  [(size_t)DMODEL * DMODEL];// fp16 w_proj

__device__ __forceinline__ uint32_t smem_u32(const void* p) {
    uint32_t a;
    asm("{ .reg .u64 t; cvta.to.shared.u64 t, %1; cvt.u32.u64 %0, t; }"
        : "=r"(a) : "l"(p));
    return a;
}

// fast exp2 via MUFU.EX2
__device__ __forceinline__ float ex2(float x) {
    float r;
    asm("ex2.approx.f32 %0, %1;" : "=f"(r) : "f"(x));
    return r;
}

// mma.sync m16n8k16 fp16 with fp32 accumulate
__device__ __forceinline__ void mma_f16(float* d, const uint32_t* a, const uint32_t* b) {
    asm volatile(
        "mma.sync.aligned.m16n8k16.row.col.f32.f16.f16.f32 "
        "{%0,%1,%2,%3}, {%4,%5,%6,%7}, {%8,%9}, {%0,%1,%2,%3};"
        : "+f"(d[0]), "+f"(d[1]), "+f"(d[2]), "+f"(d[3])
        : "r"(a[0]), "r"(a[1]), "r"(a[2]), "r"(a[3]), "r"(b[0]), "r"(b[1]));
}

__device__ __forceinline__ void ldsm_x4(uint32_t* r, uint32_t addr) {
    asm volatile("ldmatrix.sync.aligned.m8n8.x4.shared.b16 {%0,%1,%2,%3}, [%4];"
        : "=r"(r[0]), "=r"(r[1]), "=r"(r[2]), "=r"(r[3]) : "r"(addr));
}
__device__ __forceinline__ void ldsm_x2(uint32_t* r, uint32_t addr) {
    asm volatile("ldmatrix.sync.aligned.m8n8.x2.shared.b16 {%0,%1}, [%2];"
        : "=r"(r[0]), "=r"(r[1]) : "r"(addr));
}
__device__ __forceinline__ void ldsm_x2_t(uint32_t* r, uint32_t addr) {
    asm volatile("ldmatrix.sync.aligned.m8n8.x2.trans.shared.b16 {%0,%1}, [%2];"
        : "=r"(r[0]), "=r"(r[1]) : "r"(addr));
}

// ---------------------------------------------------------------------------
// C[M,N] = A[M,K] * B[N,K]^T, fp16 operands, fp32 accum. (R16 structure with
// an ALU diet: incremental global pointers + constant-offset smem addressing.)
// 128x128 CTA tile, BK=32 halves, 4-stage cp.async, one sync per chunk.
// 8 warps 2(m)x4(n), warp tile 64x32. smem row stride 40 halves.
// ---------------------------------------------------------------------------
#define GS     40
#define GSTG   (2 * 128 * GS)            // halves per stage (A+B)
#define GSTG_B (GSTG * 2)                // bytes per stage = 20480
#define GEMM_SMEM (4 * GSTG * 2)         // 81920 bytes

__global__ __launch_bounds__(256, 2) void gemm_f16(
    const __half* __restrict__ A, const __half* __restrict__ B,
    float* __restrict__ Cf, __half* __restrict__ Ch, int M, int N, int K,
    int qscale)
{
    extern __shared__ __half gsm[];

    const int tid  = threadIdx.x;
    const int lane = tid & 31;
    const int wid  = tid >> 5;
    const int wm   = wid >> 2;
    const int wn   = wid & 3;
    const int bn   = blockIdx.x;
    const int bm   = blockIdx.y;
    const int KT   = K >> 5;

    const __half* Ag = A + (size_t)bm * 128 * K;
    const __half* Bg = B + (size_t)bn * 128 * K;

    float acc[4][4][4];
#pragma unroll
    for (int mi = 0; mi < 4; ++mi)
#pragma unroll
        for (int ni = 0; ni < 4; ++ni)
#pragma unroll
            for (int r = 0; r < 4; ++r) acc[mi][ni][r] = 0.f;

    // ---- incremental fill addressing ----
    const int frow = tid >> 2;               // 0..63
    const int fcol = (tid & 3) << 3;         // 0/8/16/24 halves
    const __half* sa_ptr = Ag + (size_t)frow * K + fcol;
    const __half* sb_ptr = Bg + (size_t)frow * K + fcol;
    const uint32_t row64g = (uint32_t)(64 * K);        // halves: +64 rows in gmem
    const uint32_t sm0    = smem_u32(gsm);
    const uint32_t daoff  = (uint32_t)(frow * GS + fcol) * 2;              // bytes
    const uint32_t dboff  = (uint32_t)(128 * GS + frow * GS + fcol) * 2;   // bytes
    const uint32_t row64s = (uint32_t)(64 * GS) * 2;   // bytes: +64 rows in smem

    auto fill = [&](int c) {
        const uint32_t stb = sm0 + (uint32_t)(c & 3) * GSTG_B;
        asm volatile("cp.async.cg.shared.global [%0], [%1], 16;"
                     :: "r"(stb + daoff), "l"(sa_ptr));
        asm volatile("cp.async.cg.shared.global [%0], [%1], 16;"
                     :: "r"(stb + daoff + row64s), "l"(sa_ptr + row64g));
        asm volatile("cp.async.cg.shared.global [%0], [%1], 16;"
                     :: "r"(stb + dboff), "l"(sb_ptr));
        asm volatile("cp.async.cg.shared.global [%0], [%1], 16;"
                     :: "r"(stb + dboff + row64s), "l"(sb_ptr + row64g));
        asm volatile("cp.async.commit_group;" ::: "memory");
        sa_ptr += 32;   // next 32-half k-chunk
        sb_ptr += 32;
    };

    fill(0); fill(1); fill(2);

    // ---- constant-offset ldsm addressing (bytes within a stage) ----
    const int lane15 = lane & 15;
    const uint32_t a_base =
        (uint32_t)((wm * 64 + lane15) * GS + ((lane >> 4) << 3)) * 2;
    const uint32_t b_base =
        (uint32_t)(128 * GS + (wn * 32 + (lane & 7)) * GS
                   + (((lane >> 3) & 1) << 3)) * 2;
    const int lr = lane >> 2;
    const int lc = lane & 3;

    for (int kt = 0; kt < KT; ++kt) {
        const int rem = KT - 1 - kt;
        if (rem >= 2)      asm volatile("cp.async.wait_group 2;" ::: "memory");
        else if (rem == 1) asm volatile("cp.async.wait_group 1;" ::: "memory");
        else               asm volatile("cp.async.wait_group 0;" ::: "memory");
        __syncthreads();

        if (kt + 3 < KT) fill(kt + 3);

        const uint32_t stb = sm0 + (uint32_t)(kt & 3) * GSTG_B;
#pragma unroll
        for (int ks = 0; ks < 2; ++ks) {
            const uint32_t k0b = (uint32_t)(ks << 4) * 2;   // k offset in bytes
            uint32_t af[4][4], bf[4][2];
#pragma unroll
            for (int mi = 0; mi < 4; ++mi)
                ldsm_x4(af[mi], stb + a_base + (uint32_t)(mi * 16 * GS) * 2 + k0b);
#pragma unroll
            for (int ni = 0; ni < 4; ++ni)
                ldsm_x2(bf[ni], stb + b_base + (uint32_t)(ni * 8 * GS) * 2 + k0b);
#pragma unroll
            for (int mi = 0; mi < 4; ++mi)
#pragma unroll
                for (int ni = 0; ni < 4; ++ni)
                    mma_f16(acc[mi][ni], af[mi], bf[ni]);
        }
    }

#pragma unroll
    for (int mi = 0; mi < 4; ++mi) {
#pragma unroll
        for (int ni = 0; ni < 4; ++ni) {
            const int r0 = bm * 128 + wm * 64 + mi * 16 + lr;
            const int c0 = bn * 128 + wn * 32 + ni * 8 + lc * 2;
            const float sc = (qscale && c0 < DMODEL) ? QSCALE : 1.f;
            const float v0 = acc[mi][ni][0] * sc, v1 = acc[mi][ni][1] * sc;
            const float v2 = acc[mi][ni][2] * sc, v3 = acc[mi][ni][3] * sc;
            if (Ch) {
                *(__half2*)(Ch + (size_t)r0 * N + c0) = __floats2half2_rn(v0, v1);
                *(__half2*)(Ch + (size_t)(r0 + 8) * N + c0) = __floats2half2_rn(v2, v3);
            } else {
                *(float2*)(Cf + (size_t)r0 * N + c0)       = make_float2(v0, v1);
                *(float2*)(Cf + (size_t)(r0 + 8) * N + c0) = make_float2(v2, v3);
            }
        }
    }
}

// ---------------------------------------------------------------------------
// Merged f32 -> fp16 conversion of all three operand tensors.
// ---------------------------------------------------------------------------
#define X4  ((BT * DMODEL) / 4)
#define WQ4 ((QKVN * DMODEL) / 4)
#define WP4 ((DMODEL * DMODEL) / 4)

__global__ __launch_bounds__(256) void cvt_all_kernel(
    const float* __restrict__ x, const float* __restrict__ wq,
    const float* __restrict__ wp)
{
    int i = blockIdx.x * blockDim.x + threadIdx.x;
    const float4* src;
    __half2* dst;
    int j;
    if (i < X4)                  { src = (const float4*)x;  dst = (__half2*)g_xh;  j = i; }
    else if (i < X4 + WQ4)       { src = (const float4*)wq; dst = (__half2*)g_wqh; j = i - X4; }
    else if (i < X4 + WQ4 + WP4) { src = (const float4*)wp; dst = (__half2*)g_wph; j = i - X4 - WQ4; }
    else return;
    float4 v = src[j];
    dst[2 * j]     = __floats2half2_rn(v.x, v.y);
    dst[2 * j + 1] = __floats2half2_rn(v.z, v.w);
}

// ---------------------------------------------------------------------------
// FA2-style fp16 flash attention (unchanged from R16 — ~130us, ~92% of the
// legacy-HMMA pipe; softmax via ex2 with Q pre-scaled in the QKV epilogue).
// ---------------------------------------------------------------------------
#define AQS 72
#define ATTN_SMEM ((128 * AQS + 4 * 64 * AQS) * 2)

__global__ __launch_bounds__(256, 2) void attn_f16(__half* __restrict__ out)
{
    extern __shared__ __align__(16) __half ash[];
    __half* Qs = ash;                    // [128][72]
    __half* Kb = Qs + 128 * AQS;         // [2][64][72]
    __half* Vb = Kb + 2 * 64 * AQS;      // [2][64][72]

    const int qt   = blockIdx.x;
    const int h    = blockIdx.y;
    const int b    = blockIdx.z;
    const int tid  = threadIdx.x;
    const int lane = tid & 31;
    const int wid  = tid >> 5;          // warp owns q-rows [wid*16, wid*16+16)
    const int lr   = lane >> 2;
    const int lc   = lane & 3;
    const int lane15 = lane & 15;
    const int a_col  = (lane >> 4) << 3;
    const int b_row  = lane & 7;
    const int b_col  = ((lane >> 3) & 1) << 3;

    const size_t base = (size_t)b * TSEQ * QKVN;

    auto load_kv = [&](int kt) {
        __half* kd = Kb + (kt & 1) * 64 * AQS;
        __half* vd = Vb + (kt & 1) * 64 * AQS;
        const size_t krow = base + (size_t)(kt * 64) * QKVN + DMODEL + h * DHEAD;
        const size_t vrow = base + (size_t)(kt * 64) * QKVN + 2 * DMODEL + h * DHEAD;
#pragma unroll
        for (int u = 0; u < 2; ++u) {
            int c   = u * 256 + tid;
            int row = c >> 3;
            int col = (c & 7) << 3;
            uint32_t dk = smem_u32(kd + row * AQS + col);
            uint32_t dv = smem_u32(vd + row * AQS + col);
            const __half* sk = g_qkvh + krow + (size_t)row * QKVN + col;
            const __half* sv = g_qkvh + vrow + (size_t)row * QKVN + col;
            asm volatile("cp.async.cg.shared.global [%0], [%1], 16;" :: "r"(dk), "l"(sk));
            asm volatile("cp.async.cg.shared.global [%0], [%1], 16;" :: "r"(dv), "l"(sv));
        }
        asm volatile("cp.async.commit_group;" ::: "memory");
    };

    // prologue: Q tile (128x64) + K0/V0
#pragma unroll
    for (int u = 0; u < 4; ++u) {
        int c   = u * 256 + tid;
        int row = c >> 3;
        int col = (c & 7) << 3;
        uint32_t d = smem_u32(Qs + row * AQS + col);
        const __half* s = g_qkvh + base + (size_t)(qt * 128 + row) * QKVN + h * DHEAD + col;
        asm volatile("cp.async.cg.shared.global [%0], [%1], 16;" :: "r"(d), "l"(s));
    }
    asm volatile("cp.async.commit_group;" ::: "memory");
    load_kv(0);
    asm volatile("cp.async.wait_group 0;" ::: "memory");
    __syncthreads();

    uint32_t qf[4][4];
#pragma unroll
    for (int kc = 0; kc < 4; ++kc)
        ldsm_x4(qf[kc], smem_u32(Qs + (wid * 16 + lane15) * AQS + kc * 16 + a_col));

    float m0 = -INFINITY, m1 = -INFINITY, l0 = 0.f, l1 = 0.f;
    float o[8][4];
#pragma unroll
    for (int nb = 0; nb < 8; ++nb)
#pragma unroll
        for (int r = 0; r < 4; ++r) o[nb][r] = 0.f;

    for (int kt = 0; kt < NKT; ++kt) {
        if (kt + 1 < NKT) load_kv(kt + 1);

        const __half* Ks = Kb + (kt & 1) * 64 * AQS;
        const __half* Vs = Vb + (kt & 1) * 64 * AQS;

        // ---- S = Q * K^T ----
        float s[8][4];
#pragma unroll
        for (int nb = 0; nb < 8; ++nb)
#pragma unroll
            for (int r = 0; r < 4; ++r) s[nb][r] = 0.f;

#pragma unroll
        for (int kc = 0; kc < 4; ++kc) {
            uint32_t bf[8][2];
#pragma unroll
            for (int nb = 0; nb < 8; ++nb)
                ldsm_x2(bf[nb], smem_u32(Ks + (nb * 8 + b_row) * AQS
                                            + kc * 16 + b_col));
#pragma unroll
            for (int nb = 0; nb < 8; ++nb)
                mma_f16(s[nb], qf[kc], bf[nb]);
        }

        // ---- online softmax (ex2; scale pre-folded into Q) ----
        float mx0 = s[0][0], mx1 = s[0][2];
#pragma unroll
        for (int nb = 0; nb < 8; ++nb) {
            mx0 = fmaxf(mx0, fmaxf(s[nb][0], s[nb][1]));
            mx1 = fmaxf(mx1, fmaxf(s[nb][2], s[nb][3]));
        }
        mx0 = fmaxf(mx0, __shfl_xor_sync(0xffffffffu, mx0, 1));
        mx0 = fmaxf(mx0, __shfl_xor_sync(0xffffffffu, mx0, 2));
        mx1 = fmaxf(mx1, __shfl_xor_sync(0xffffffffu, mx1, 1));
        mx1 = fmaxf(mx1, __shfl_xor_sync(0xffffffffu, mx1, 2));

        const float mn0 = fmaxf(m0, mx0);
        const float mn1 = fmaxf(m1, mx1);
        const float e0 = ex2(m0 - mn0);
        const float e1 = ex2(m1 - mn1);
        m0 = mn0; m1 = mn1;

        uint32_t pf[4][4];
        float ls0 = 0.f, ls1 = 0.f;
#pragma unroll
        for (int kc = 0; kc < 4; ++kc) {
#pragma unroll
            for (int half_id = 0; half_id < 2; ++half_id) {
                const int nb = 2 * kc + half_id;
                float p00 = ex2(s[nb][0] - mn0);
                float p01 = ex2(s[nb][1] - mn0);
                float p10 = ex2(s[nb][2] - mn1);
                float p11 = ex2(s[nb][3] - mn1);
                __half2 h0 = __floats2half2_rn(p00, p01);
                __half2 h1 = __floats2half2_rn(p10, p11);
                ls0 += __low2float(h0) + __high2float(h0);
                ls1 += __low2float(h1) + __high2float(h1);
                pf[kc][half_id * 2]     = *(uint32_t*)&h0;
                pf[kc][half_id * 2 + 1] = *(uint32_t*)&h1;
            }
        }
        ls0 += __shfl_xor_sync(0xffffffffu, ls0, 1);
        ls0 += __shfl_xor_sync(0xffffffffu, ls0, 2);
        ls1 += __shfl_xor_sync(0xffffffffu, ls1, 1);
        ls1 += __shfl_xor_sync(0xffffffffu, ls1, 2);
        l0 = l0 * e0 + ls0;
        l1 = l1 * e1 + ls1;

#pragma unroll
        for (int nb = 0; nb < 8; ++nb) {
            o[nb][0] *= e0; o[nb][1] *= e0;
            o[nb][2] *= e1; o[nb][3] *= e1;
        }

        // ---- O += P * V ----
#pragma unroll
        for (int kc = 0; kc < 4; ++kc) {
            uint32_t bv[8][2];
#pragma unroll
            for (int nb = 0; nb < 8; ++nb)
                ldsm_x2_t(bv[nb], smem_u32(Vs + (kc * 16 + lane15) * AQS + nb * 8));
#pragma unroll
            for (int nb = 0; nb < 8; ++nb)
                mma_f16(o[nb], pf[kc], bv[nb]);
        }

        if (kt + 1 < NKT) {
            asm volatile("cp.async.wait_group 0;" ::: "memory");
            __syncthreads();
        }
    }

    const float inv0 = 1.f / l0;
    const float inv1 = 1.f / l1;
    const size_t r0 = (size_t)b * TSEQ + qt * 128 + wid * 16 + lr;
#pragma unroll
    for (int nb = 0; nb < 8; ++nb) {
        const int c0 = h * DHEAD + nb * 8 + lc * 2;
        *(__half2*)(out + r0 * DMODEL + c0) =
            __floats2half2_rn(o[nb][0] * inv0, o[nb][1] * inv0);
        *(__half2*)(out + (r0 + 8) * DMODEL + c0) =
            __floats2half2_rn(o[nb][2] * inv1, o[nb][3] * inv1);
    }
}

// ---------------------------------------------------------------------------
extern "C" void kernel_launch(void* const* d_in, const int* in_sizes, int n_in,
                              void* d_out, int out_size)
{
    const float* x      = (const float*)d_in[0];   // [2,2048,1024]
    const float* w_qkv  = (const float*)d_in[1];   // [3072,1024]
    const float* w_proj = (const float*)d_in[2];   // [1024,1024]
    float* out = (float*)d_out;                    // [2,2048,1024]

    __half *qkvh, *attnh, *xh, *wqh, *wph;
    cudaGetSymbolAddress((void**)&qkvh,  g_qkvh);
    cudaGetSymbolAddress((void**)&attnh, g_attnh);
    cudaGetSymbolAddress((void**)&xh,    g_xh);
    cudaGetSymbolAddress((void**)&wqh,   g_wqh);
    cudaGetSymbolAddress((void**)&wph,   g_wph);

    cudaFuncSetAttribute(gemm_f16,
                         cudaFuncAttributeMaxDynamicSharedMemorySize, GEMM_SMEM);
    cudaFuncSetAttribute(attn_f16,
                         cudaFuncAttributeMaxDynamicSharedMemorySize, ATTN_SMEM);

    // 0) f32 -> fp16 conversion of all operands (one launch)
    {
        int total = X4 + WQ4 + WP4;
        cvt_all_kernel<<<(total + 255) / 256, 256>>>(x, w_qkv, w_proj);
    }

    // 1) QKV projection -> fp16 qkv (Q columns pre-scaled by QSCALE)
    {
        dim3 g(QKVN / 128, BT / 128);
        gemm_f16<<<g, 256, GEMM_SMEM>>>(xh, wqh, nullptr, qkvh, BT, QKVN, DMODEL, 1);
    }

    // 2) FA2-style fp16 flash attention -> fp16 attn
    {
        dim3 ga(TSEQ / 128, HEADS, NBATCH);
        attn_f16<<<ga, 256, ATTN_SMEM>>>(attnh);
    }

    // 3) Output projection -> fp32 out
    {
        dim3 g(DMODEL / 128, BT / 128);
        gemm_f16<<<g, 256, GEMM_SMEM>>>(attnh, wph, out, nullptr, BT, DMODEL, DMODEL, 0);
    }
}